// round 3
// baseline (speedup 1.0000x reference)
#include <cuda_runtime.h>
#include <cstdint>

// ---------------------------------------------------------------------------
// AdditiveGaussianIMDPCertifier: iterated CSR row-sum
//   gamma_new[j] = clip(1 - sum_k b[j,k] * (1 - gamma[nbr[j,k]]), 0, 1)
//
// Strategy: column-tiled SpMV. Edges are stably partitioned (in-launch) by
// neighbor tile (32768 floats = 128KB smem), packed to 4B/edge
// (15-bit tile-local idx | 16-bit fixed-point b), so every gather is served
// from shared memory instead of random L2 sectors.
//
// Inputs (metadata order):
//   d_in[0] gamma0       float32 [n]
//   d_in[1] bound_lower  float32 [ne]     (b < 1/128 by construction)
//   d_in[2] neighbor_idx int32   [ne]
//   d_in[3] segment_ids  int32   [ne]     (sorted)
//   d_in[4] horizon      int32   [1]
// Output: float32 [n]
// ---------------------------------------------------------------------------

#define MAX_N    262144
#define NT_MAX   8
#define MAX_E    27000000
#define TILE_LOG 15
#define TILE     (1 << TILE_LOG)     // 32768 floats = 128KB smem
#define HMAX     16
#define CHUNK    4096                // rows per CTA in step kernel
#define QSCALE   2097152.0f          // 2^21
#define QINV     (1.0f / 2097152.0f)

__device__ int      g_row_ptr[MAX_N + 1];
__device__ int      g_rtp[NT_MAX * MAX_N + 1];   // counts -> exclusive scan -> CSR ptr per (tile,row)
__device__ unsigned g_packed[MAX_E];             // (qb << 16) | local_idx
__device__ int      g_bsum[8192];
__device__ float    g_gamma[MAX_N];
__device__ float    g_accum[MAX_N];

// ---------------- preprocessing ----------------

// row_ptr[j] = lower_bound(segment_ids, j)
__global__ void build_row_ptr_kernel(const int* __restrict__ seg, int n_edges, int n) {
    int j = blockIdx.x * blockDim.x + threadIdx.x;
    if (j > n) return;
    int lo = 0, hi = n_edges;
    while (lo < hi) {
        int mid = (lo + hi) >> 1;
        if (__ldg(&seg[mid]) < j) lo = mid + 1;
        else                      hi = mid;
    }
    g_row_ptr[j] = lo;
}

__global__ void init_kernel(const float* __restrict__ g0, int n) {
    int i = blockIdx.x * blockDim.x + threadIdx.x;
    if (i < n) { g_gamma[i] = g0[i]; g_accum[i] = 0.0f; }
}

// Warp per row: count edges per (tile,row) via match_any ranking.
__global__ void count_kernel(const int* __restrict__ nbr, int n, int NT) {
    __shared__ int base[8][NT_MAX + 1];
    int warp = (blockIdx.x * blockDim.x + threadIdx.x) >> 5;
    int lane = threadIdx.x & 31;
    int ws   = threadIdx.x >> 5;
    if (warp >= n) return;
    if (lane <= NT_MAX) base[ws][lane] = 0;
    __syncwarp();

    int beg = g_row_ptr[warp], end = g_row_ptr[warp + 1];
    int iters = (end - beg + 31) >> 5;
    for (int i = 0; i < iters; i++) {
        int e = beg + i * 32 + lane;
        int t = (e < end) ? (__ldg(&nbr[e]) >> TILE_LOG) : NT_MAX;
        unsigned m = __match_any_sync(0xffffffffu, t);
        int lt = __popc(m & ((1u << lane) - 1u));
        int b0 = base[ws][t];
        __syncwarp();
        if (lt == 0) base[ws][t] = b0 + __popc(m);
        __syncwarp();
    }
    if (lane < NT) g_rtp[lane * n + warp] = base[ws][lane];
}

// Exclusive scan of g_rtp[0..L), 3-kernel, in place.
__global__ void scan1_kernel(int L) {
    __shared__ int sd[1024];
    int idx = blockIdx.x * 1024 + threadIdx.x;
    int x = (idx < L) ? g_rtp[idx] : 0;
    sd[threadIdx.x] = x; __syncthreads();
    for (int off = 1; off < 1024; off <<= 1) {
        int v = (threadIdx.x >= off) ? sd[threadIdx.x - off] : 0;
        __syncthreads();
        sd[threadIdx.x] += v;
        __syncthreads();
    }
    if (idx < L) g_rtp[idx] = sd[threadIdx.x] - x;
    if (threadIdx.x == 1023) g_bsum[blockIdx.x] = sd[1023];
}

__global__ void scan2_kernel(int nb) {
    __shared__ int sd[1024];
    __shared__ int run;
    if (threadIdx.x == 0) run = 0;
    __syncthreads();
    for (int basei = 0; basei < nb; basei += 1024) {
        int idx = basei + threadIdx.x;
        int x = (idx < nb) ? g_bsum[idx] : 0;
        sd[threadIdx.x] = x; __syncthreads();
        for (int off = 1; off < 1024; off <<= 1) {
            int v = (threadIdx.x >= off) ? sd[threadIdx.x - off] : 0;
            __syncthreads();
            sd[threadIdx.x] += v;
            __syncthreads();
        }
        int incl = sd[threadIdx.x];
        if (idx < nb) g_bsum[idx] = incl - x + run;
        __syncthreads();
        if (threadIdx.x == 1023) run += incl;
        __syncthreads();
    }
}

__global__ void scan3_kernel(int L, int ne) {
    int idx = blockIdx.x * 1024 + threadIdx.x;
    if (idx < L) g_rtp[idx] += g_bsum[idx >> 10];
    if (idx == 0) g_rtp[L] = ne;
}

// Warp per row: recompute ranks, emit packed edges grouped by (tile,row).
__global__ void pack_kernel(const int* __restrict__ nbr, const float* __restrict__ bl,
                            int n, int NT) {
    __shared__ int base[8][NT_MAX + 1];
    int warp = (blockIdx.x * blockDim.x + threadIdx.x) >> 5;
    int lane = threadIdx.x & 31;
    int ws   = threadIdx.x >> 5;
    if (warp >= n) return;
    if (lane <= NT_MAX) base[ws][lane] = 0;
    __syncwarp();

    int beg = g_row_ptr[warp], end = g_row_ptr[warp + 1];
    int iters = (end - beg + 31) >> 5;
    for (int i = 0; i < iters; i++) {
        int e = beg + i * 32 + lane;
        bool valid = (e < end);
        int idx = valid ? __ldg(&nbr[e]) : 0;
        int t   = valid ? (idx >> TILE_LOG) : NT_MAX;
        unsigned m = __match_any_sync(0xffffffffu, t);
        int lt = __popc(m & ((1u << lane) - 1u));
        int b0 = base[ws][t];
        __syncwarp();
        if (lt == 0) base[ws][t] = b0 + __popc(m);
        __syncwarp();
        if (valid) {
            unsigned qb = __float2uint_rn(__ldg(&bl[e]) * QSCALE);   // < 16384, fits 16b
            unsigned pk = (qb << 16) | (unsigned)(idx & (TILE - 1));
            g_packed[g_rtp[t * n + warp] + b0 + lt] = pk;
        }
    }
}

// ---------------- per-step kernels ----------------

extern __shared__ float smv[];   // TILE floats: 1 - gamma[tile]

__global__ void __launch_bounds__(1024, 1)
step_kernel(int n, int tstep, const int* __restrict__ hor) {
    if (tstep >= __ldg(hor)) return;
    int t  = blockIdx.y;
    int tb = t << TILE_LOG;
    for (int i = threadIdx.x; i < TILE; i += 1024) {
        int gi = tb + i;
        smv[i] = (gi < n) ? 1.0f - g_gamma[gi] : 0.0f;
    }
    __syncthreads();

    int warp = threadIdx.x >> 5;
    int lane = threadIdx.x & 31;
    int row0 = blockIdx.x * CHUNK;
    int rend = min(row0 + CHUNK, n);
    int pbase = t * n;

    for (int row = row0 + warp; row < rend; row += 32) {
        int beg = __ldg(&g_rtp[pbase + row]);
        int end = __ldg(&g_rtp[pbase + row + 1]);
        float s = 0.0f;
        for (int e = beg + lane; e < end; e += 32) {
            unsigned p = __ldg(&g_packed[e]);
            s += (float)(p >> 16) * smv[p & (TILE - 1)];
        }
        #pragma unroll
        for (int o = 16; o; o >>= 1) s += __shfl_xor_sync(0xffffffffu, s, o);
        if (lane == 0 && s != 0.0f) atomicAdd(&g_accum[row], s * QINV);
    }
}

__global__ void finalize_kernel(int n, int tstep, const int* __restrict__ hor) {
    int i = blockIdx.x * blockDim.x + threadIdx.x;
    if (i >= n) return;
    if (tstep >= __ldg(hor)) { g_accum[i] = 0.0f; return; }   // identity step
    float g = 1.0f - g_accum[i];
    g_gamma[i] = fminf(fmaxf(g, 0.0f), 1.0f);
    g_accum[i] = 0.0f;
}

__global__ void writeout_kernel(float* __restrict__ out, int n) {
    int i = blockIdx.x * blockDim.x + threadIdx.x;
    if (i < n) out[i] = g_gamma[i];
}

// ---------------- launch ----------------

extern "C" void kernel_launch(void* const* d_in, const int* in_sizes, int n_in,
                              void* d_out, int out_size) {
    const float* gamma0 = (const float*)d_in[0];
    const float* bl     = (const float*)d_in[1];
    const int*   nbr    = (const int*)d_in[2];
    const int*   seg    = (const int*)d_in[3];
    const int*   hor    = (const int*)d_in[4];

    int n  = in_sizes[0];
    int ne = in_sizes[1];
    int NT = (n + TILE - 1) / TILE;
    int L  = NT * n;

    build_row_ptr_kernel<<<(n + 1 + 255) / 256, 256>>>(seg, ne, n);
    init_kernel<<<(n + 255) / 256, 256>>>(gamma0, n);

    count_kernel<<<(n + 7) / 8, 256>>>(nbr, n, NT);

    int sblk = (L + 1023) / 1024;
    scan1_kernel<<<sblk, 1024>>>(L);
    scan2_kernel<<<1, 1024>>>(sblk);
    scan3_kernel<<<sblk, 1024>>>(L, ne);

    pack_kernel<<<(n + 7) / 8, 256>>>(nbr, bl, n, NT);

    cudaFuncSetAttribute((const void*)step_kernel,
                         cudaFuncAttributeMaxDynamicSharedMemorySize, TILE * 4);
    dim3 sg((n + CHUNK - 1) / CHUNK, NT);
    for (int t = 0; t < HMAX; t++) {
        step_kernel<<<sg, 1024, TILE * 4>>>(n, t, hor);
        finalize_kernel<<<(n + 255) / 256, 256>>>(n, t, hor);
    }

    writeout_kernel<<<(n + 255) / 256, 256>>>((float*)d_out, n);
}

// round 4
// speedup vs baseline: 2.1985x; 2.1985x over previous
#include <cuda_runtime.h>
#include <cstdint>

// ---------------------------------------------------------------------------
// AdditiveGaussianIMDPCertifier: iterated CSR row-sum
//   gamma_new[j] = clip(1 - sum_k b[j,k] * (1 - gamma[nbr[j,k]]), 0, 1)
//
// Strategy: column-tiled SpMV with transposed-ELL slabs.
//  - gamma partitioned into tiles of 32768 floats (128KB smem).
//  - Edges packed to 4B: (qb<<16)|local_idx, qb = round(b * 2^21) fits 16b.
//  - For each (32-row group, tile): edges stored column-major slab[i*32+lane],
//    zero-padded to group max segment length. Step kernel = thread-per-row,
//    register accumulator across tiles, fully coalesced loads, smem gathers.
//    No atomics, no shuffles, no per-row pointer loads in the hot loop.
// ---------------------------------------------------------------------------

#define MAX_N    262144
#define NT_MAX   8
#define MAX_RAW  27000000
#define MAX_PACK 67108864         // padded entries (dataset ~43.4M)
#define TILE_LOG 15
#define TILE     (1 << TILE_LOG)  // 32768 floats = 128KB
#define HMAX     16
#define QSCALE   2097152.0f       // 2^21
#define QINV     (1.0f / 2097152.0f)
#define ROWS_CTA 1024
#define CAP      12288            // pack2 staging entries (48KB)

__device__ int      g_row_ptr[MAX_N + 1];
__device__ int      g_rtp[NT_MAX * MAX_N + 1];      // per-(tile,row) CSR ptrs (global scan)
__device__ int      g_off[(MAX_N / 32) * NT_MAX + 1]; // per-(group,tile) slab offsets
__device__ unsigned g_tmp[MAX_RAW];                 // tile-partitioned, row-contiguous
__device__ unsigned g_packed[MAX_PACK];             // transposed ELL slabs
__device__ int      g_bsum[8192];
__device__ float    g_gamma[2][MAX_N];

// ---------------- preprocessing ----------------

__global__ void build_row_ptr_kernel(const int* __restrict__ seg, int n_edges, int n) {
    int j = blockIdx.x * blockDim.x + threadIdx.x;
    if (j > n) return;
    int lo = 0, hi = n_edges;
    while (lo < hi) {
        int mid = (lo + hi) >> 1;
        if (__ldg(&seg[mid]) < j) lo = mid + 1;
        else                      hi = mid;
    }
    g_row_ptr[j] = lo;
}

__global__ void init_kernel(const float* __restrict__ g0, int n) {
    int i = blockIdx.x * blockDim.x + threadIdx.x;
    if (i < n) g_gamma[0][i] = g0[i];
}

// Warp per row: count edges per (tile,row) via match_any ranking.
__global__ void count_kernel(const int* __restrict__ nbr, int n, int NP, int NT) {
    __shared__ int base[8][NT_MAX + 1];
    int warp = (blockIdx.x * blockDim.x + threadIdx.x) >> 5;
    int lane = threadIdx.x & 31;
    int ws   = threadIdx.x >> 5;
    if (blockIdx.x == 0 && threadIdx.x == 0) g_rtp[NT * NP] = 0;  // scan sentinel
    if (warp >= NP) return;
    if (warp >= n) { if (lane < NT) g_rtp[lane * NP + warp] = 0; return; }
    if (lane <= NT_MAX) base[ws][lane] = 0;
    __syncwarp();

    int beg = g_row_ptr[warp], end = g_row_ptr[warp + 1];
    int iters = (end - beg + 31) >> 5;
    for (int i = 0; i < iters; i++) {
        int e = beg + i * 32 + lane;
        int t = (e < end) ? (__ldg(&nbr[e]) >> TILE_LOG) : NT_MAX;
        unsigned m = __match_any_sync(0xffffffffu, t);
        int lt = __popc(m & ((1u << lane) - 1u));
        int b0 = base[ws][t];
        __syncwarp();
        if (lt == 0) base[ws][t] = b0 + __popc(m);
        __syncwarp();
    }
    if (lane < NT) g_rtp[lane * NP + warp] = base[ws][lane];
}

// --- 3-kernel exclusive scan, in place; sel: 0 -> g_rtp, 1 -> g_off ---
__device__ __forceinline__ int* scan_arr(int sel) { return sel ? g_off : g_rtp; }

__global__ void scan1_kernel(int sel, int Ls) {
    int* arr = scan_arr(sel);
    __shared__ int sd[1024];
    int idx = blockIdx.x * 1024 + threadIdx.x;
    int x = (idx < Ls) ? arr[idx] : 0;
    sd[threadIdx.x] = x; __syncthreads();
    for (int off = 1; off < 1024; off <<= 1) {
        int v = (threadIdx.x >= off) ? sd[threadIdx.x - off] : 0;
        __syncthreads();
        sd[threadIdx.x] += v;
        __syncthreads();
    }
    if (idx < Ls) arr[idx] = sd[threadIdx.x] - x;
    if (threadIdx.x == 1023) g_bsum[blockIdx.x] = sd[1023];
}

__global__ void scan2_kernel(int nb) {
    __shared__ int sd[1024];
    __shared__ int run;
    if (threadIdx.x == 0) run = 0;
    __syncthreads();
    for (int basei = 0; basei < nb; basei += 1024) {
        int idx = basei + threadIdx.x;
        int x = (idx < nb) ? g_bsum[idx] : 0;
        sd[threadIdx.x] = x; __syncthreads();
        for (int off = 1; off < 1024; off <<= 1) {
            int v = (threadIdx.x >= off) ? sd[threadIdx.x - off] : 0;
            __syncthreads();
            sd[threadIdx.x] += v;
            __syncthreads();
        }
        int incl = sd[threadIdx.x];
        if (idx < nb) g_bsum[idx] = incl - x + run;
        __syncthreads();
        if (threadIdx.x == 1023) run += incl;
        __syncthreads();
    }
}

__global__ void scan3_kernel(int sel, int Ls) {
    int* arr = scan_arr(sel);
    int idx = blockIdx.x * 1024 + threadIdx.x;
    if (idx < Ls) arr[idx] += g_bsum[idx >> 10];
}

// Warp per row: recompute ranks, emit packed edges grouped (tile, row-contig).
__global__ void pack1_kernel(const int* __restrict__ nbr, const float* __restrict__ bl,
                             int n, int NP, int NT) {
    __shared__ int base[8][NT_MAX + 1];
    int warp = (blockIdx.x * blockDim.x + threadIdx.x) >> 5;
    int lane = threadIdx.x & 31;
    int ws   = threadIdx.x >> 5;
    if (warp >= n) return;
    if (lane <= NT_MAX) base[ws][lane] = 0;
    __syncwarp();

    int beg = g_row_ptr[warp], end = g_row_ptr[warp + 1];
    int iters = (end - beg + 31) >> 5;
    for (int i = 0; i < iters; i++) {
        int e = beg + i * 32 + lane;
        bool valid = (e < end);
        int idx = valid ? __ldg(&nbr[e]) : 0;
        int t   = valid ? (idx >> TILE_LOG) : NT_MAX;
        unsigned m = __match_any_sync(0xffffffffu, t);
        int lt = __popc(m & ((1u << lane) - 1u));
        int b0 = base[ws][t];
        __syncwarp();
        if (lt == 0) base[ws][t] = b0 + __popc(m);
        __syncwarp();
        if (valid) {
            unsigned qb = __float2uint_rn(__ldg(&bl[e]) * QSCALE);
            unsigned pk = (qb << 16) | (unsigned)(idx & (TILE - 1));
            g_tmp[g_rtp[t * NP + warp] + b0 + lt] = pk;
        }
    }
}

// Warp per (group,tile): slab size = 32 * max segment length within the group.
__global__ void widthoff_kernel(int G, int NT, int NP) {
    int gt   = (blockIdx.x * blockDim.x + threadIdx.x) >> 5;
    int lane = threadIdx.x & 31;
    int L2 = G * NT;
    if (blockIdx.x == 0 && threadIdx.x == 0) g_off[L2] = 0;  // scan sentinel
    if (gt >= L2) return;
    int g = gt / NT, t = gt - g * NT;
    int idx = t * NP + g * 32 + lane;
    int len = g_rtp[idx + 1] - g_rtp[idx];
    #pragma unroll
    for (int o = 16; o; o >>= 1) len = max(len, __shfl_xor_sync(0xffffffffu, len, o));
    if (lane == 0) g_off[gt] = len << 5;
}

// CTA per (group,tile): transpose row-contiguous segments into column-major
// slab (i*32 + lane), zero-padding to width W. Chunked smem staging keeps
// both reads and writes coalesced; fallback loop handles any span size.
__global__ void pack2_kernel(int G, int NT, int NP) {
    __shared__ unsigned stg[CAP];
    int g = blockIdx.x, t = blockIdx.y;
    int tid = threadIdx.x, lane = tid & 31;
    int rbase = t * NP + g * 32;
    int span_beg = g_rtp[rbase];
    int span_end = g_rtp[rbase + 32];
    int sl  = g_rtp[rbase + lane];
    int len = g_rtp[rbase + lane + 1] - sl;
    int gt = g * NT + t;
    int O  = g_off[gt];
    int W  = (g_off[gt + 1] - O) >> 5;

    for (int s0 = span_beg; s0 < span_end || s0 == span_beg; s0 += CAP) {
        int cend = min(s0 + CAP, span_end);
        for (int j = tid; j < cend - s0; j += 128) stg[j] = g_tmp[s0 + j];
        __syncthreads();
        for (int i = tid >> 5; i < W; i += 4) {
            int pos = sl + i;
            if (i < len) {
                if (pos >= s0 && pos < cend)
                    g_packed[O + i * 32 + lane] = stg[pos - s0];
            } else if (s0 == span_beg) {
                g_packed[O + i * 32 + lane] = 0u;   // padding: qb=0, idx=0
            }
        }
        __syncthreads();
    }
}

// ---------------- step kernel ----------------

extern __shared__ float smv[];   // TILE floats: 1 - gamma[tile]

__global__ void __launch_bounds__(1024, 1)
step_kernel(int n, int G, int NT, int tstep, int parity, const int* __restrict__ hor) {
    const float* __restrict__ gin  = g_gamma[parity];
    float*       __restrict__ gout = g_gamma[parity ^ 1];
    int tid = threadIdx.x;
    int row = blockIdx.x * ROWS_CTA + tid;

    if (tstep >= __ldg(hor)) {                 // identity step (uniform branch)
        if (row < n) gout[row] = gin[row];
        return;
    }

    int g    = row >> 5;
    int lane = row & 31;
    bool active = (g < G);
    float acc = 0.0f;

    for (int tt = 0; tt < NT; tt++) {
        int tb = tt << TILE_LOG;
        for (int i = tid; i < TILE; i += 1024) {
            int gi = tb + i;
            smv[i] = (gi < n) ? 1.0f - gin[gi] : 0.0f;
        }
        __syncthreads();

        if (active) {
            int gt = g * NT + tt;
            int O = __ldg(&g_off[gt]);
            int W = (__ldg(&g_off[gt + 1]) - O) >> 5;
            const unsigned* __restrict__ p = g_packed + O + lane;
            #pragma unroll 4
            for (int i = 0; i < W; i++) {
                unsigned v = __ldg(&p[i * 32]);
                acc += (float)(v >> 16) * smv[v & (TILE - 1)];
            }
        }
        __syncthreads();
    }

    if (row < n) {
        float gv = 1.0f - acc * QINV;
        gout[row] = fminf(fmaxf(gv, 0.0f), 1.0f);
    }
}

__global__ void writeout_kernel(float* __restrict__ out, int n) {
    int i = blockIdx.x * blockDim.x + threadIdx.x;
    if (i < n) out[i] = g_gamma[0][i];    // HMAX even -> result in buffer 0
}

// ---------------- launch ----------------

extern "C" void kernel_launch(void* const* d_in, const int* in_sizes, int n_in,
                              void* d_out, int out_size) {
    const float* gamma0 = (const float*)d_in[0];
    const float* bl     = (const float*)d_in[1];
    const int*   nbr    = (const int*)d_in[2];
    const int*   seg    = (const int*)d_in[3];
    const int*   hor    = (const int*)d_in[4];

    int n  = in_sizes[0];
    int ne = in_sizes[1];
    int G  = (n + 31) / 32;
    int NP = G * 32;
    int NT = (n + TILE - 1) / TILE;

    build_row_ptr_kernel<<<(n + 1 + 255) / 256, 256>>>(seg, ne, n);
    init_kernel<<<(n + 255) / 256, 256>>>(gamma0, n);

    // count -> scan(rtp) -> pack1 (tile-partitioned, row-contiguous)
    count_kernel<<<(NP + 7) / 8, 256>>>(nbr, n, NP, NT);
    {
        int Ls = NT * NP + 1;
        int nb = (Ls + 1023) / 1024;
        scan1_kernel<<<nb, 1024>>>(0, Ls);
        scan2_kernel<<<1, 1024>>>(nb);
        scan3_kernel<<<nb, 1024>>>(0, Ls);
    }
    pack1_kernel<<<(n + 7) / 8, 256>>>(nbr, bl, n, NP, NT);

    // widths -> scan(off) -> pack2 (transposed ELL slabs)
    widthoff_kernel<<<(G * NT + 7) / 8, 256>>>(G, NT, NP);
    {
        int Ls = G * NT + 1;
        int nb = (Ls + 1023) / 1024;
        scan1_kernel<<<nb, 1024>>>(1, Ls);
        scan2_kernel<<<1, 1024>>>(nb);
        scan3_kernel<<<nb, 1024>>>(1, Ls);
    }
    {
        dim3 pg(G, NT);
        pack2_kernel<<<pg, 128>>>(G, NT, NP);
    }

    // time propagation
    cudaFuncSetAttribute((const void*)step_kernel,
                         cudaFuncAttributeMaxDynamicSharedMemorySize, TILE * 4);
    int sb = (NP + ROWS_CTA - 1) / ROWS_CTA;
    for (int t = 0; t < HMAX; t++) {
        step_kernel<<<sb, 1024, TILE * 4>>>(n, G, NT, t, t & 1, hor);
    }

    writeout_kernel<<<(n + 255) / 256, 256>>>((float*)d_out, n);
}

// round 6
// speedup vs baseline: 2.6087x; 1.1866x over previous
#include <cuda_runtime.h>
#include <cstdint>

// ---------------------------------------------------------------------------
// AdditiveGaussianIMDPCertifier: iterated CSR row-sum
//   gamma_new[j] = clip(1 - sum_k b[j,k] * (1 - gamma[nbr[j,k]]), 0, 1)
//
// v5: tile-resident column-tiled SpMV over transposed-ELL slabs.
//  - Preprocessing collapsed to ONE kernel (block per 32-row group):
//    in-block binary search, count, width-max, atomicAdd slab allocation
//    (order-free, output-deterministic), swizzled smem staging, coalesced out.
//  - Step kernel: CTA = (tile, row-chunk). Loads its 128KB gamma tile ONCE,
//    one barrier, then warps stream whole ELL slabs (coalesced LDG + smem
//    gather + FFMA), writing per-(tile,row) partials (no atomics).
//  - Finalize sums NT partials per row, clips, ping-pongs gamma.
// ---------------------------------------------------------------------------

#define MAX_N    262144
#define MAX_G    (MAX_N / 32)
#define NT_MAX   8
#define TILE_LOG 15
#define TILE     (1 << TILE_LOG)      // 32768 floats = 128KB smem
#define HMAX     16
#define QSCALE   2097152.0f           // 2^21 (b < 1/128 -> qb <= 16384)
#define QINV     (1.0f / 2097152.0f)
#define MAX_PACK 50331648             // 48M padded entries (expect ~38M)
#define CAPE     24576                // prep stage entries (96KB smem)
#define SPLIT    21                   // row-chunks: grid = NT*SPLIT = 147 CTAs

__device__ int      g_total;
__device__ int      g_soff[MAX_G * NT_MAX];      // slab offset per (group,tile)
__device__ int      g_swid[MAX_G * NT_MAX];      // slab width  per (group,tile)
__device__ unsigned g_packed[MAX_PACK];          // ELL slabs: (qb<<16)|local_idx
__device__ float    g_partial[NT_MAX * MAX_N];   // per-(tile,row) partial sums
__device__ float    g_gamma[2][MAX_N];

__global__ void zero_kernel() { g_total = 0; }

// bank swizzle: rotate lane by row index within 32-entry blocks (bijective)
__device__ __forceinline__ unsigned SW(unsigned k) {
    return (k & ~31u) | ((k + (k >> 5)) & 31u);
}

// ---------------- preprocessing: one kernel, block per group ----------------

extern __shared__ unsigned dynsh[];

__global__ void __launch_bounds__(1024, 1)
prep_kernel(const float* __restrict__ g0, const float* __restrict__ bl,
            const int* __restrict__ nbr, const int* __restrict__ seg,
            int n, int ne, int G, int NT)
{
    unsigned* stage = dynsh;                        // CAPE entries
    __shared__ int rp[33];
    __shared__ int cnt[32][NT_MAX + 1];
    __shared__ int sW[NT_MAX], sLB[NT_MAX];
    __shared__ int sBase, sTot, sOvf;

    int g = blockIdx.x;
    int tid = threadIdx.x, w = tid >> 5, lane = tid & 31;

    // row_ptr for the group's 33 fence posts (binary search on sorted seg)
    if (tid < 33) {
        int j = g * 32 + tid; if (j > n) j = n;
        int lo = 0, hi = ne;
        while (lo < hi) { int m = (lo + hi) >> 1; if (__ldg(&seg[m]) < j) lo = m + 1; else hi = m; }
        rp[tid] = lo;
    }
    if (tid < 32) {                                  // gamma init for own rows
        int row = g * 32 + tid;
        if (row < n) g_gamma[0][row] = g0[row];
    }
    if (lane <= NT_MAX) cnt[w][lane] = 0;
    __syncthreads();

    // pass 1: per-(row,tile) counts via match_any ranking (warp w = row w)
    int beg = rp[w], end = rp[w + 1];
    int iters = (end - beg + 31) >> 5;
    for (int i = 0; i < iters; i++) {
        int e = beg + i * 32 + lane;
        int t = (e < end) ? (__ldg(&nbr[e]) >> TILE_LOG) : NT_MAX;
        unsigned m = __match_any_sync(0xffffffffu, t);
        int lt = __popc(m & ((1u << lane) - 1u));
        int b0 = cnt[w][t];
        __syncwarp();
        if (lt == 0) cnt[w][t] = b0 + __popc(m);
        __syncwarp();
    }
    __syncthreads();

    // widths per tile = max over 32 rows; serial prefix; bump allocation
    if (tid < NT) {
        int W = 0;
        for (int r = 0; r < 32; r++) W = max(W, cnt[r][tid]);
        sW[tid] = W;
    }
    __syncthreads();
    if (tid == 0) {
        int lb = 0;
        for (int t = 0; t < NT; t++) { sLB[t] = lb; lb += sW[t] * 32; }
        sTot = lb;
        int base = atomicAdd(&g_total, lb);
        sBase = base;
        sOvf = (lb > CAPE) ? 1 : 0;
        if (base + lb > MAX_PACK) sOvf = 2;          // pathological: skip
        for (int t = 0; t < NT; t++) {
            g_soff[g * NT + t] = base + sLB[t];
            g_swid[g * NT + t] = (sOvf == 2) ? 0 : sW[t];
        }
    }
    __syncthreads();
    if (sOvf == 2) return;

    // zero stage (padding entries become 0 => qb=0, idx=0), reset ranks
    if (!sOvf) for (int k = tid; k < sTot; k += 1024) stage[k] = 0u;
    if (lane <= NT_MAX) cnt[w][lane] = 0;
    __syncthreads();

    // pass 2: recompute ranks, place edges into swizzled smem slab
    for (int i = 0; i < iters; i++) {
        int e = beg + i * 32 + lane;
        bool valid = (e < end);
        int ix = valid ? __ldg(&nbr[e]) : 0;
        int t  = valid ? (ix >> TILE_LOG) : NT_MAX;
        unsigned m = __match_any_sync(0xffffffffu, t);
        int lt = __popc(m & ((1u << lane) - 1u));
        int b0 = cnt[w][t];
        __syncwarp();
        if (lt == 0) cnt[w][t] = b0 + __popc(m);
        __syncwarp();
        if (valid) {
            unsigned qb = __float2uint_rn(__ldg(&bl[e]) * QSCALE);
            unsigned pk = (qb << 16) | (unsigned)(ix & (TILE - 1));
            unsigned local = (unsigned)(sLB[t] + (b0 + lt) * 32 + w);
            if (!sOvf) stage[SW(local)] = pk;
            else       g_packed[sBase + local] = pk;
        }
    }

    if (sOvf) {   // rare fallback: zero the padding directly in global
        for (int t = 0; t < NT; t++)
            for (int i = cnt[w][t] + lane; i < sW[t]; i += 32)
                g_packed[sBase + sLB[t] + i * 32 + w] = 0u;
        return;
    }

    __syncthreads();
    // coalesced copy-out (reads are conflict-free through SW)
    for (int k = tid; k < sTot; k += 1024)
        g_packed[sBase + k] = stage[SW((unsigned)k)];
}

// ---------------- step: tile-resident CTAs ----------------

__global__ void __launch_bounds__(1024, 1)
step_kernel(int n, int G, int NT, int GPC, int tstep, int parity,
            const int* __restrict__ hor)
{
    if (tstep >= __ldg(hor)) return;                // finalize does the copy
    float* smv = (float*)dynsh;                     // TILE floats: 1-gamma
    const float* __restrict__ gin = g_gamma[parity];

    int t  = blockIdx.x;
    int tb = t << TILE_LOG;
    int tid = threadIdx.x;

    // vectorized tile fill (in-bounds reads: g_gamma is MAX_N-sized)
    for (int i = tid; i < TILE / 4; i += 1024) {
        int gi = tb + 4 * i;
        float4 v = *(const float4*)(gin + gi);
        float4 o;
        o.x = (gi + 0 < n) ? 1.0f - v.x : 0.0f;
        o.y = (gi + 1 < n) ? 1.0f - v.y : 0.0f;
        o.z = (gi + 2 < n) ? 1.0f - v.z : 0.0f;
        o.w = (gi + 3 < n) ? 1.0f - v.w : 0.0f;
        ((float4*)smv)[i] = o;
    }
    __syncthreads();

    int w = tid >> 5, lane = tid & 31;
    int gbeg = blockIdx.y * GPC;
    int gend = min(gbeg + GPC, G);

    for (int g = gbeg + w; g < gend; g += 32) {
        int gt  = g * NT + t;
        int off = __ldg(&g_soff[gt]);
        int wid = __ldg(&g_swid[gt]);
        const unsigned* __restrict__ p = g_packed + off + lane;
        float acc = 0.0f;
        #pragma unroll 4
        for (int i = 0; i < wid; i++) {
            unsigned v = __ldg(&p[i * 32]);
            acc += (float)(v >> 16) * smv[v & (TILE - 1)];
        }
        g_partial[t * MAX_N + g * 32 + lane] = acc;
    }
}

__global__ void finalize_kernel(int n, int NT, int tstep, int parity,
                                const int* __restrict__ hor)
{
    int i = blockIdx.x * blockDim.x + threadIdx.x;
    if (i >= n) return;
    const float* __restrict__ gin  = g_gamma[parity];
    float*       __restrict__ gout = g_gamma[parity ^ 1];
    if (tstep >= __ldg(hor)) { gout[i] = gin[i]; return; }
    float s = 0.0f;
    #pragma unroll
    for (int t = 0; t < NT_MAX; t++)
        if (t < NT) s += g_partial[t * MAX_N + i];
    float gv = 1.0f - s * QINV;
    gout[i] = fminf(fmaxf(gv, 0.0f), 1.0f);
}

__global__ void writeout_kernel(float* __restrict__ out, int n) {
    int i = blockIdx.x * blockDim.x + threadIdx.x;
    if (i < n) out[i] = g_gamma[0][i];   // HMAX even -> result in buffer 0
}

// ---------------- launch ----------------

extern "C" void kernel_launch(void* const* d_in, const int* in_sizes, int n_in,
                              void* d_out, int out_size) {
    const float* gamma0 = (const float*)d_in[0];
    const float* bl     = (const float*)d_in[1];
    const int*   nbr    = (const int*)d_in[2];
    const int*   seg    = (const int*)d_in[3];
    const int*   hor    = (const int*)d_in[4];

    int n  = in_sizes[0];
    int ne = in_sizes[1];
    int G  = (n + 31) / 32;
    int NT = (n + TILE - 1) / TILE;
    int GPC = (G + SPLIT - 1) / SPLIT;

    zero_kernel<<<1, 1>>>();

    cudaFuncSetAttribute((const void*)prep_kernel,
                         cudaFuncAttributeMaxDynamicSharedMemorySize, CAPE * 4);
    prep_kernel<<<G, 1024, CAPE * 4>>>(gamma0, bl, nbr, seg, n, ne, G, NT);

    cudaFuncSetAttribute((const void*)step_kernel,
                         cudaFuncAttributeMaxDynamicSharedMemorySize, TILE * 4);
    dim3 sg(NT, SPLIT);
    for (int t = 0; t < HMAX; t++) {
        step_kernel<<<sg, 1024, TILE * 4>>>(n, G, NT, GPC, t, t & 1, hor);
        finalize_kernel<<<(n + 255) / 256, 256>>>(n, NT, t, t & 1, hor);
    }

    writeout_kernel<<<(n + 255) / 256, 256>>>((float*)d_out, n);
}

// round 7
// speedup vs baseline: 5.0208x; 1.9246x over previous
#include <cuda_runtime.h>
#include <cstdint>

// ---------------------------------------------------------------------------
// AdditiveGaussianIMDPCertifier: iterated CSR row-sum
//   gamma_new[j] = clip(1 - sum_k b[j,k] * (1 - gamma[nbr[j,k]]), 0, 1)
//
// v7: tile-resident column-tiled SpMV over transposed ELL slabs, uint4 lanes.
//  - row_ptr built by a dedicated parallel binary-search kernel.
//  - prep (block per 32-row group): count via match_any, width rounded to 4,
//    atomicAdd bump allocation (placement-order free -> deterministic values),
//    32KB swizzled smem staging (2 CTAs/SM), coalesced copy-out.
//  - slab layout: entry j of row w at (j>>2)*128 + w*4 + (j&3) -> each lane
//    loads uint4 = 4 edges of its row (LDG.128, 512B/warp).
//  - step: CTA = (tile, row-chunk); 128KB gamma tile in smem, one barrier,
//    then pure coalesced LDG.128 + smem gather + FFMA; per-(tile,row)
//    partials, no atomics. finalize sums NT partials, clips, ping-pongs.
// ---------------------------------------------------------------------------

#define MAX_N    262144
#define MAX_G    (MAX_N / 32)
#define NT_MAX   8
#define TILE_LOG 15
#define TILE     (1 << TILE_LOG)      // 32768 floats = 128KB smem
#define HMAX     16
#define QSCALE   2097152.0f           // 2^21 (b < 1/128 -> qb <= 16384)
#define QINV     (1.0f / 2097152.0f)
#define MAX_PACK 50331648             // padded entries cap (expect ~38M)
#define CAPE     8192                 // prep staging entries (32KB smem)
#define SPLIT    21                   // grid = NT*SPLIT = 147 CTAs

__device__ int      g_total;
__device__ int      g_row_ptr[MAX_N + 1];
__device__ int      g_soff[MAX_G * NT_MAX];      // slab offset per (group,tile)
__device__ int      g_swid[MAX_G * NT_MAX];      // slab width (mult of 4)
__device__ uint4    g_packed4[MAX_PACK / 4];     // ELL slabs
#define g_packed ((unsigned*)g_packed4)
__device__ float    g_partial[NT_MAX * MAX_N];   // per-(tile,row) partials
__device__ float    g_gamma[2][MAX_N];

// bank swizzle: rotate lane by 32-entry block index (bijective within stage)
__device__ __forceinline__ unsigned SW(unsigned k) {
    return (k & ~31u) | ((k + (k >> 5)) & 31u);
}

extern __shared__ unsigned dynsh[];

// ---------------- launch 0: row_ptr + init ----------------

__global__ void rowptr_kernel(const int* __restrict__ seg, int ne, int n) {
    int j = blockIdx.x * blockDim.x + threadIdx.x;
    if (j == 0) g_total = 0;
    if (j > n) return;
    int lo = 0, hi = ne;
    while (lo < hi) {
        int m = (lo + hi) >> 1;
        if (__ldg(&seg[m]) < j) lo = m + 1;
        else                    hi = m;
    }
    g_row_ptr[j] = lo;
}

// ---------------- launch 1: prep (block per 32-row group) ----------------

__global__ void __launch_bounds__(1024, 2)
prep_kernel(const float* __restrict__ g0, const float* __restrict__ bl,
            const int* __restrict__ nbr, int n, int G, int NT)
{
    unsigned* stage = dynsh;                       // CAPE entries (32KB)
    __shared__ int rp[33];
    __shared__ int cnt[32][NT_MAX + 1];
    __shared__ int sW[NT_MAX], sLB[NT_MAX];
    __shared__ int sBase, sTot, sOvf;

    int g = blockIdx.x;
    int tid = threadIdx.x, w = tid >> 5, lane = tid & 31;

    if (tid < 33) {
        int j = g * 32 + tid; if (j > n) j = n;
        rp[tid] = g_row_ptr[j];
    }
    if (tid < 32) {
        int row = g * 32 + tid;
        if (row < n) g_gamma[0][row] = g0[row];
    }
    if (lane <= NT_MAX) cnt[w][lane] = 0;
    __syncthreads();

    // pass 1: per-(row,tile) counts via match_any ranking (warp w = row w)
    int beg = rp[w], end = rp[w + 1];
    int iters = (end - beg + 31) >> 5;
    for (int i = 0; i < iters; i++) {
        int e = beg + i * 32 + lane;
        int t = (e < end) ? (__ldg(&nbr[e]) >> TILE_LOG) : NT_MAX;
        unsigned m = __match_any_sync(0xffffffffu, t);
        int lt = __popc(m & ((1u << lane) - 1u));
        int b0 = cnt[w][t];
        __syncwarp();
        if (lt == 0) cnt[w][t] = b0 + __popc(m);
        __syncwarp();
    }
    __syncthreads();

    // widths (max over 32 rows, rounded to multiple of 4); bump allocation
    if (tid < NT) {
        int W = 0;
        for (int r = 0; r < 32; r++) W = max(W, cnt[r][tid]);
        sW[tid] = (W + 3) & ~3;
    }
    __syncthreads();
    if (tid == 0) {
        int lb = 0;
        for (int t = 0; t < NT; t++) { sLB[t] = lb; lb += sW[t] * 32; }
        sTot = lb;
        int base = atomicAdd(&g_total, lb);
        sBase = base;
        sOvf = (lb > CAPE) ? 1 : 0;
        if (base + lb > MAX_PACK) sOvf = 2;        // pathological: drop group
        for (int t = 0; t < NT; t++) {
            g_soff[g * NT + t] = base + sLB[t];
            g_swid[g * NT + t] = (sOvf == 2) ? 0 : sW[t];
        }
    }
    __syncthreads();
    if (sOvf == 2) return;

    if (!sOvf) for (int k = tid; k < sTot; k += 1024) stage[k] = 0u;
    if (lane <= NT_MAX) cnt[w][lane] = 0;
    __syncthreads();

    // pass 2: recompute ranks, place edges (uint4-lane layout)
    for (int i = 0; i < iters; i++) {
        int e = beg + i * 32 + lane;
        bool valid = (e < end);
        int ix = valid ? __ldg(&nbr[e]) : 0;
        int t  = valid ? (ix >> TILE_LOG) : NT_MAX;
        unsigned m = __match_any_sync(0xffffffffu, t);
        int lt = __popc(m & ((1u << lane) - 1u));
        int b0 = cnt[w][t];
        __syncwarp();
        if (lt == 0) cnt[w][t] = b0 + __popc(m);
        __syncwarp();
        if (valid) {
            unsigned qb = __float2uint_rn(__ldg(&bl[e]) * QSCALE);
            unsigned pk = (qb << 16) | (unsigned)(ix & (TILE - 1));
            int j = b0 + lt;
            unsigned local = (unsigned)(sLB[t] + ((j >> 2) << 7) + (w << 2) + (j & 3));
            if (!sOvf) stage[SW(local)] = pk;
            else       g_packed[sBase + local] = pk;
        }
    }

    if (sOvf) {   // rare: zero the padding directly in global, uncoalesced OK
        for (int t = 0; t < NT; t++)
            for (int j = cnt[w][t] + lane; j < sW[t]; j += 32)
                g_packed[sBase + sLB[t] + ((j >> 2) << 7) + (w << 2) + (j & 3)] = 0u;
        return;
    }

    __syncthreads();
    for (int k = tid; k < sTot; k += 1024)     // coalesced copy-out
        g_packed[sBase + k] = stage[SW((unsigned)k)];
}

// ---------------- launch 2: dummy (aligns ncu capture to step0) ------------

__global__ void dummy_kernel() {}

// ---------------- step: tile-resident CTAs ----------------

__global__ void __launch_bounds__(1024, 1)
step_kernel(int n, int G, int NT, int GPC, int tstep, int parity,
            const int* __restrict__ hor)
{
    if (tstep >= __ldg(hor)) return;               // finalize does the copy
    float* smv = (float*)dynsh;                    // TILE floats: 1 - gamma
    const float* __restrict__ gin = g_gamma[parity];

    int t  = blockIdx.x;
    int tb = t << TILE_LOG;
    int tid = threadIdx.x;

    for (int i = tid; i < TILE / 4; i += 1024) {
        int gi = tb + 4 * i;
        float4 v = *(const float4*)(gin + gi);     // in-bounds: MAX_N-sized
        float4 o;
        o.x = (gi + 0 < n) ? 1.0f - v.x : 0.0f;
        o.y = (gi + 1 < n) ? 1.0f - v.y : 0.0f;
        o.z = (gi + 2 < n) ? 1.0f - v.z : 0.0f;
        o.w = (gi + 3 < n) ? 1.0f - v.w : 0.0f;
        ((float4*)smv)[i] = o;
    }
    __syncthreads();

    int w = tid >> 5, lane = tid & 31;
    int gbeg = blockIdx.y * GPC;
    int gend = min(gbeg + GPC, G);

    for (int g = gbeg + w; g < gend; g += 32) {
        int gt  = g * NT + t;
        int off = __ldg(&g_soff[gt]);
        int nb4 = __ldg(&g_swid[gt]) >> 2;
        const uint4* __restrict__ p = (const uint4*)(g_packed + off) + lane;
        float acc = 0.0f;
        #pragma unroll 2
        for (int i = 0; i < nb4; i++) {
            uint4 v = __ldg(&p[i * 32]);
            acc += (float)(v.x >> 16) * smv[v.x & (TILE - 1)];
            acc += (float)(v.y >> 16) * smv[v.y & (TILE - 1)];
            acc += (float)(v.z >> 16) * smv[v.z & (TILE - 1)];
            acc += (float)(v.w >> 16) * smv[v.w & (TILE - 1)];
        }
        g_partial[t * MAX_N + g * 32 + lane] = acc;
    }
}

__global__ void finalize_kernel(int n, int NT, int tstep, int parity,
                                const int* __restrict__ hor)
{
    int i = blockIdx.x * blockDim.x + threadIdx.x;
    if (i >= n) return;
    const float* __restrict__ gin  = g_gamma[parity];
    float*       __restrict__ gout = g_gamma[parity ^ 1];
    if (tstep >= __ldg(hor)) { gout[i] = gin[i]; return; }
    float s = 0.0f;
    #pragma unroll
    for (int t = 0; t < NT_MAX; t++)
        if (t < NT) s += g_partial[t * MAX_N + i];
    float gv = 1.0f - s * QINV;
    gout[i] = fminf(fmaxf(gv, 0.0f), 1.0f);
}

__global__ void writeout_kernel(float* __restrict__ out, int n) {
    int i = blockIdx.x * blockDim.x + threadIdx.x;
    if (i < n) out[i] = g_gamma[0][i];   // HMAX even -> result in buffer 0
}

// ---------------- launch ----------------

extern "C" void kernel_launch(void* const* d_in, const int* in_sizes, int n_in,
                              void* d_out, int out_size) {
    const float* gamma0 = (const float*)d_in[0];
    const float* bl     = (const float*)d_in[1];
    const int*   nbr    = (const int*)d_in[2];
    const int*   seg    = (const int*)d_in[3];
    const int*   hor    = (const int*)d_in[4];

    int n  = in_sizes[0];
    int ne = in_sizes[1];
    int G  = (n + 31) / 32;
    int NT = (n + TILE - 1) / TILE;
    int GPC = (G + SPLIT - 1) / SPLIT;

    rowptr_kernel<<<(n + 1 + 255) / 256, 256>>>(seg, ne, n);          // #0

    cudaFuncSetAttribute((const void*)prep_kernel,
                         cudaFuncAttributeMaxDynamicSharedMemorySize, CAPE * 4);
    prep_kernel<<<G, 1024, CAPE * 4>>>(gamma0, bl, nbr, n, G, NT);    // #1

    dummy_kernel<<<1, 32>>>();                                        // #2

    cudaFuncSetAttribute((const void*)step_kernel,
                         cudaFuncAttributeMaxDynamicSharedMemorySize, TILE * 4);
    dim3 sg(NT, SPLIT);
    for (int t = 0; t < HMAX; t++) {                                  // #3 = step0
        step_kernel<<<sg, 1024, TILE * 4>>>(n, G, NT, GPC, t, t & 1, hor);
        finalize_kernel<<<(n + 255) / 256, 256>>>(n, NT, t, t & 1, hor);
    }

    writeout_kernel<<<(n + 255) / 256, 256>>>((float*)d_out, n);
}